// round 17
// baseline (speedup 1.0000x reference)
#include <cuda_runtime.h>

#define B 4
#define C 32
#define H 256
#define W 256
#define H3 768
#define W3 768
#define PLANE_IN  65536
#define PLANE_OUT 589824
#define STRIP 8                // input row-groups per block
#define NTHR 288               // (96 chunks) x (3 kx)

// 32-byte evict_first store
__device__ __forceinline__ void stg_ef_8f(float* p, const float* v) {
    const unsigned long long a = *reinterpret_cast<const unsigned long long*>(v + 0);
    const unsigned long long b = *reinterpret_cast<const unsigned long long*>(v + 2);
    const unsigned long long c = *reinterpret_cast<const unsigned long long*>(v + 4);
    const unsigned long long d = *reinterpret_cast<const unsigned long long*>(v + 6);
    asm volatile("st.global.L2::evict_first.v4.b64 [%0], {%1,%2,%3,%4};"
                 :: "l"(p), "l"(a), "l"(b), "l"(c), "l"(d) : "memory");
}

// out[p, I, J] = x[p, reflect(I/3+I%3-1), reflect(J/3+J%3-1)]
//                * (I==767?2:1) * (J==767?2:1)
// Direct: no smem. 4 scalar L1-cached gathers + selects -> one 32B store.
__global__ __launch_bounds__(NTHR)
void deform_direct32_kernel(const float* __restrict__ x, float* __restrict__ out) {
    const int tid   = threadIdx.x;
    const int base  = blockIdx.x * STRIP;
    const int plane = blockIdx.y;

    const float* __restrict__ xp = x + (size_t)plane * PLANE_IN;

    const int c8 = tid % 96;                // output 8-float chunk in row
    const int kx = tid / 96;                // 0..2
    const int J0 = 8 * c8;

    // 8 output cols J0..J0+7 gather 4 consecutive input cols lo..lo+3,
    // permutation selected by r = J0 mod 3:
    //   r=0: {0,1,2,1,2,3,2,3}  r=1: {0,1,0,1,2,1,2,3}  r=2: {1,0,1,2,1,2,3,2}
    const int  r3  = J0 % 3;
    const bool pr0 = (r3 == 0);
    const bool pr2 = (r3 == 2);
    const int  lo  = J0 / 3 - (pr0 ? 1 : 0);
    // column clamps (reflection): col -1 -> x[1] (t=0 only, reads c0 at lo=-1);
    // col 256 -> x[254] (c8=95, r3=1, reads c3 at lo+3=256)
    int cc0 = lo,     cc1 = lo + 1, cc2 = lo + 2, cc3 = lo + 3;
    if (cc0 < 0)     cc0 = 1;
    if (cc3 > W - 1) cc3 = W - 2;

    const float wlast = (c8 == 95) ? 2.0f : 1.0f;   // J=767 weight (e==7)

    float* __restrict__ opl = out + (size_t)plane * PLANE_OUT;

#pragma unroll
    for (int g = 0; g < STRIP; ++g) {
        const int ig = base + g;
        // input row for out row 3*ig+kx = reflect(ig + kx - 1)
        int ri = ig + kx - 1;
        if (ri < 0)     ri = 1;
        if (ri > H - 1) ri = H - 2;
        const float* __restrict__ r = xp + ri * W;

        const float L0 = __ldg(r + cc0);
        const float L1 = __ldg(r + cc1);
        const float L2 = __ldg(r + cc2);
        const float L3 = __ldg(r + cc3);

        float v[8];
        v[0] = pr2 ? L1 : L0;
        v[1] = pr2 ? L0 : L1;
        v[2] = pr0 ? L2 : (pr2 ? L1 : L0);
        v[3] = pr2 ? L2 : L1;
        v[4] = pr2 ? L1 : L2;
        v[5] = pr0 ? L3 : (pr2 ? L2 : L1);
        v[6] = pr2 ? L3 : L2;
        v[7] = (pr2 ? L2 : L3) * wlast;     // J=767: weight 2

        if (kx == 2 && ig == H - 1) {       // output row I=767: weight 2
#pragma unroll
            for (int e = 0; e < 8; ++e)
                v[e] *= 2.0f;
        }
        stg_ef_8f(opl + (size_t)(3 * ig + kx) * W3 + J0, v);
    }
}

extern "C" void kernel_launch(void* const* d_in, const int* in_sizes, int n_in,
                              void* d_out, int out_size) {
    const float* x = (const float*)d_in[0];
    float* out = (float*)d_out;
    (void)in_sizes; (void)n_in; (void)out_size;

    dim3 grid(H / STRIP, B * C);   // 32 x 128 = 4096 blocks
    deform_direct32_kernel<<<grid, NTHR>>>(x, out);
}